// round 2
// baseline (speedup 1.0000x reference)
#include <cuda_runtime.h>
#include <cuda_bf16.h>

#define T 1024
#define D 1024
#define H 16
#define DHD 64
#define DFF 4096

// ---------------- static scratch (device globals; no allocation) ----------------
__device__ float g_hs[T * D];
__device__ float g_hbuf[T * D];
__device__ float g_q[T * D];
__device__ float g_k[T * D];
__device__ float g_v[T * D];
__device__ float g_beta[T * H];
__device__ float g_o[T * D];
__device__ float g_kc[T * D];
__device__ float g_vc[T * D];
__device__ float g_kcr[T * D];
__device__ float g_scores[(size_t)H * T * T];
__device__ float g_ff1[T * DFF];
__device__ float g_ff2[T * DFF];
__device__ float g_cos[T * 32];
__device__ float g_sin[T * 32];

// ---------------- embedding gather ----------------
__global__ void embed_k(const int* __restrict__ ids, const float* __restrict__ emb,
                        float* __restrict__ out) {
    int t = blockIdx.x;
    int id = ids[t];
    for (int i = threadIdx.x; i < D; i += 256)
        out[(size_t)t * D + i] = emb[(size_t)id * D + i];
}

// ---------------- rope tables ----------------
__global__ void rope_tab_k(float* __restrict__ ct, float* __restrict__ st) {
    int t = blockIdx.x, i = threadIdx.x;  // i in [0,32)
    float inv = __powf(10000.0f, -(float)i / 32.0f);
    float f = (float)t * inv;
    ct[t * 32 + i] = cosf(f);
    st[t * 32 + i] = sinf(f);
}

// rope apply on [T, H, 64]; in may equal out
__global__ void rope_apply_k(const float* __restrict__ in, float* __restrict__ out,
                             const float* __restrict__ ct, const float* __restrict__ st) {
    int idx = blockIdx.x * 256 + threadIdx.x;  // T*H*32 total
    if (idx >= T * H * 32) return;
    int d = idx & 31;
    int th = idx >> 5;
    int h = th & (H - 1);
    int t = th >> 4;
    float c = ct[t * 32 + d], s = st[t * 32 + d];
    const float* pi = in + (size_t)t * D + h * DHD;
    float* po = out + (size_t)t * D + h * DHD;
    float x0 = pi[d], x1 = pi[d + 32];
    po[d] = x0 * c - x1 * s;
    po[d + 32] = x1 * c + x0 * s;
}

// ---------------- packed f32x2 FMA (Blackwell FFMA2; PTX-only path) ----------------
__device__ __forceinline__ unsigned long long fma2(unsigned long long a, unsigned long long b,
                                                   unsigned long long c) {
    unsigned long long d;
    asm("fma.rn.f32x2 %0, %1, %2, %3;" : "=l"(d) : "l"(a), "l"(b), "l"(c));
    return d;
}

// ---------------- generic GEMM: C = act(A@B + bias) [*mul] [+res] ----------------
// act: 0 none, 1 silu, 2 sigmoid.  batched over blockIdx.z with strides sA,sB,sC.
// 64x64 tile, 128 threads, 8 rows x 4 cols per thread via packed f32x2 FMA.
__global__ __launch_bounds__(128) void gemm_k(
        const float* __restrict__ A, const float* __restrict__ Bm,
        const float* __restrict__ bias, const float* __restrict__ mulb,
        const float* __restrict__ resb, float* __restrict__ C,
        int M, int N, int K, int lda, int ldb, int ldc,
        long sA, long sB, long sC, int act) {
    int bz = blockIdx.z;
    A += (long)bz * sA;
    Bm += (long)bz * sB;
    C += (long)bz * sC;
    const float* mulp = mulb ? mulb + (long)bz * sC : nullptr;
    const float* resp = resb ? resb + (long)bz * sC : nullptr;

    int bm = blockIdx.y * 64, bn = blockIdx.x * 64;
    __shared__ float2 As2[16][64];  // A values duplicated into both halves
    __shared__ float Bs[16][64];

    int tid = threadIdx.x;          // 128 threads
    int ty = tid >> 4;              // 0..7  -> rows ty*8..+7
    int tx = tid & 15;              // 0..15 -> cols tx*4..+3

    // stage-load mapping
    int arow = tid >> 1;            // 0..63
    int akq = (tid & 1) * 8;        // 0 or 8
    int bkr = tid >> 4;             // 0..7 (also loads bkr+8)
    int bn4 = (tid & 15) * 4;

    float aP[8];
    float bPa[4], bPb[4];

    auto gload = [&](int k0) {
        int gm = bm + arow;
#pragma unroll
        for (int i = 0; i < 8; i++)
            aP[i] = (gm < M) ? A[(long)gm * lda + k0 + akq + i] : 0.f;
        int gn = bn + bn4;
#pragma unroll
        for (int i = 0; i < 4; i++) {
            bPa[i] = (gn + i < N) ? Bm[(long)(k0 + bkr) * ldb + gn + i] : 0.f;
            bPb[i] = (gn + i < N) ? Bm[(long)(k0 + bkr + 8) * ldb + gn + i] : 0.f;
        }
    };
    auto sstore = [&]() {
#pragma unroll
        for (int i = 0; i < 8; i++) As2[akq + i][arow] = make_float2(aP[i], aP[i]);
#pragma unroll
        for (int i = 0; i < 4; i++) {
            Bs[bkr][bn4 + i] = bPa[i];
            Bs[bkr + 8][bn4 + i] = bPb[i];
        }
    };

    unsigned long long acc[8][2];
#pragma unroll
    for (int r = 0; r < 8; r++) {
        acc[r][0] = 0ull;
        acc[r][1] = 0ull;
    }

    gload(0);
    sstore();
    __syncthreads();

    for (int k0 = 0; k0 < K; k0 += 16) {
        bool more = (k0 + 16) < K;
        if (more) gload(k0 + 16);

#pragma unroll
        for (int kk = 0; kk < 16; kk++) {
            const ulonglong2* ap = (const ulonglong2*)&As2[kk][ty * 8];
            ulonglong2 a01 = ap[0];
            ulonglong2 a23 = ap[1];
            ulonglong2 a45 = ap[2];
            ulonglong2 a67 = ap[3];
            ulonglong2 bb = *(const ulonglong2*)&Bs[kk][tx * 4];
            acc[0][0] = fma2(a01.x, bb.x, acc[0][0]);
            acc[0][1] = fma2(a01.x, bb.y, acc[0][1]);
            acc[1][0] = fma2(a01.y, bb.x, acc[1][0]);
            acc[1][1] = fma2(a01.y, bb.y, acc[1][1]);
            acc[2][0] = fma2(a23.x, bb.x, acc[2][0]);
            acc[2][1] = fma2(a23.x, bb.y, acc[2][1]);
            acc[3][0] = fma2(a23.y, bb.x, acc[3][0]);
            acc[3][1] = fma2(a23.y, bb.y, acc[3][1]);
            acc[4][0] = fma2(a45.x, bb.x, acc[4][0]);
            acc[4][1] = fma2(a45.x, bb.y, acc[4][1]);
            acc[5][0] = fma2(a45.y, bb.x, acc[5][0]);
            acc[5][1] = fma2(a45.y, bb.y, acc[5][1]);
            acc[6][0] = fma2(a67.x, bb.x, acc[6][0]);
            acc[6][1] = fma2(a67.x, bb.y, acc[6][1]);
            acc[7][0] = fma2(a67.y, bb.x, acc[7][0]);
            acc[7][1] = fma2(a67.y, bb.y, acc[7][1]);
        }
        __syncthreads();
        if (more) {
            sstore();
            __syncthreads();
        }
    }

    // epilogue
#pragma unroll
    for (int r = 0; r < 8; r++) {
        int gm = bm + ty * 8 + r;
        if (gm >= M) continue;
        float vals[4];
        float2 c01 = *(float2*)&acc[r][0];
        float2 c23 = *(float2*)&acc[r][1];
        vals[0] = c01.x;
        vals[1] = c01.y;
        vals[2] = c23.x;
        vals[3] = c23.y;
#pragma unroll
        for (int j = 0; j < 4; j++) {
            int gn = bn + tx * 4 + j;
            if (gn >= N) continue;
            float v = vals[j];
            if (bias) v += bias[gn];
            if (act == 1) v = v / (1.f + __expf(-v));
            else if (act == 2) v = 1.f / (1.f + __expf(-v));
            if (mulp) v *= mulp[(long)gm * ldc + gn];
            if (resp) v += resp[(long)gm * ldc + gn];
            C[(long)gm * ldc + gn] = v;
        }
    }
}

// ---------------- group norm over 64 (l2norm or rmsnorm*w) ----------------
__global__ void groupnorm64_k(float* __restrict__ x, const float* __restrict__ w, int mode) {
    int g = blockIdx.x * 8 + (threadIdx.x >> 5);  // group over T*H
    int lane = threadIdx.x & 31;
    float* p = x + (size_t)g * 64;
    float a = p[lane], b = p[lane + 32];
    float s = a * a + b * b;
#pragma unroll
    for (int off = 16; off; off >>= 1) s += __shfl_xor_sync(0xffffffffu, s, off);
    float r = (mode == 0) ? rsqrtf(s + 1e-6f) : rsqrtf(s * (1.f / 64.f) + 1e-6f);
    float wa = mode ? w[lane] : 1.f;
    float wb = mode ? w[lane + 32] : 1.f;
    p[lane] = a * r * wa;
    p[lane + 32] = b * r * wb;
}

// ---------------- row rmsnorm over D ----------------
__global__ void rmsnorm_row_k(const float* __restrict__ x, const float* __restrict__ w,
                              float* __restrict__ out) {
    int t = blockIdx.x;
    const float* p = x + (size_t)t * D;
    __shared__ float red[256];
    float s = 0.f;
    for (int i = threadIdx.x; i < D; i += 256) {
        float v = p[i];
        s += v * v;
    }
    red[threadIdx.x] = s;
    __syncthreads();
    for (int off = 128; off; off >>= 1) {
        if (threadIdx.x < off) red[threadIdx.x] += red[threadIdx.x + off];
        __syncthreads();
    }
    float r = rsqrtf(red[0] * (1.f / D) + 1e-6f);
    for (int i = threadIdx.x; i < D; i += 256)
        out[(size_t)t * D + i] = p[i] * r * w[i];
}

// ---------------- DeltaNet sequential scan ----------------
__global__ void deltanet_scan_k(const float* __restrict__ q, const float* __restrict__ k,
                                const float* __restrict__ v, const float* __restrict__ beta,
                                float* __restrict__ o) {
    int h = blockIdx.x;
    int tid = threadIdx.x;
    int j = tid >> 2;
    int r = tid & 3;
    __shared__ float sk[2][64], sq[2][64], sv[2][64], sb[2];

    float s[16];
#pragma unroll
    for (int i = 0; i < 16; i++) s[i] = 0.f;

    if (tid < 64) sk[0][tid] = k[(size_t)h * 64 + tid];
    else if (tid < 128) sq[0][tid - 64] = q[(size_t)h * 64 + (tid - 64)];
    else if (tid < 192) sv[0][tid - 128] = v[(size_t)h * 64 + (tid - 128)];
    else if (tid == 192) sb[0] = beta[h];
    __syncthreads();

    for (int t = 0; t < T; t++) {
        int cur = t & 1, nxt = cur ^ 1;
        float pre = 0.f;
        bool havePre = (t + 1 < T) && (tid <= 192);
        if (havePre) {
            int tt = t + 1;
            if (tid < 64) pre = k[(size_t)tt * D + h * 64 + tid];
            else if (tid < 128) pre = q[(size_t)tt * D + h * 64 + (tid - 64)];
            else if (tid < 192) pre = v[(size_t)tt * D + h * 64 + (tid - 128)];
            else pre = beta[tt * H + h];
        }

        float p0 = 0.f, p1 = 0.f;
#pragma unroll
        for (int i = 0; i < 16; i += 2) {
            p0 += sk[cur][r * 16 + i] * s[i];
            p1 += sk[cur][r * 16 + i + 1] * s[i + 1];
        }
        float p = p0 + p1;
        p += __shfl_xor_sync(0xffffffffu, p, 1);
        p += __shfl_xor_sync(0xffffffffu, p, 2);

        float delta = sb[cur] * (sv[cur][j] - p);

        float o0 = 0.f, o1 = 0.f;
#pragma unroll
        for (int i = 0; i < 16; i += 2) {
            s[i] += sk[cur][r * 16 + i] * delta;
            o0 += sq[cur][r * 16 + i] * s[i];
            s[i + 1] += sk[cur][r * 16 + i + 1] * delta;
            o1 += sq[cur][r * 16 + i + 1] * s[i + 1];
        }
        float oo = o0 + o1;
        oo += __shfl_xor_sync(0xffffffffu, oo, 1);
        oo += __shfl_xor_sync(0xffffffffu, oo, 2);
        if (r == 0) o[(size_t)t * D + h * 64 + j] = oo;

        if (havePre) {
            if (tid < 64) sk[nxt][tid] = pre;
            else if (tid < 128) sq[nxt][tid - 64] = pre;
            else if (tid < 192) sv[nxt][tid - 128] = pre;
            else sb[nxt] = pre;
        }
        __syncthreads();
    }
}

// ---------------- attention scores: per-head tril(QK^T)/8 ----------------
__global__ void attn_scores_k(const float* __restrict__ q, const float* __restrict__ kk,
                              float* __restrict__ scores) {
    int h = blockIdx.z;
    int t0 = blockIdx.y * 32, s0 = blockIdx.x * 32;
    size_t base = (size_t)h * T * T;
    int tid = threadIdx.x;

    if (s0 > t0 + 31) {  // fully masked tile
        for (int idx = tid; idx < 1024; idx += 256) {
            int tt = idx >> 5, ss = idx & 31;
            scores[base + (size_t)(t0 + tt) * T + s0 + ss] = -1e30f;
        }
        return;
    }

    __shared__ float sQ[32][65], sK[32][65];
    for (int idx = tid; idx < 2048; idx += 256) {
        int rr = idx >> 6, cc = idx & 63;
        sQ[rr][cc] = q[(size_t)(t0 + rr) * D + h * 64 + cc];
        sK[rr][cc] = kk[(size_t)(s0 + rr) * D + h * 64 + cc];
    }
    __syncthreads();

    int sl = tid & 31, tg = tid >> 5;
#pragma unroll
    for (int i = 0; i < 4; i++) {
        int tt = tg + i * 8;
        float acc = 0.f;
#pragma unroll
        for (int d = 0; d < 64; d++) acc += sQ[tt][d] * sK[sl][d];
        int gt = t0 + tt, gs = s0 + sl;
        scores[base + (size_t)gt * T + gs] = (gs <= gt) ? acc * 0.125f : -1e30f;
    }
}

// ---------------- row softmax over 1024 ----------------
__global__ void softmax_k(float* __restrict__ scores) {
    size_t row = blockIdx.x;  // h*T + t
    float* p = scores + row * T;
    __shared__ float red[256];
    int tid = threadIdx.x;

    float v4[4];
    float m = -1e30f;
#pragma unroll
    for (int i = 0; i < 4; i++) {
        v4[i] = p[tid + i * 256];
        m = fmaxf(m, v4[i]);
    }
    red[tid] = m;
    __syncthreads();
    for (int off = 128; off; off >>= 1) {
        if (tid < off) red[tid] = fmaxf(red[tid], red[tid + off]);
        __syncthreads();
    }
    m = red[0];
    __syncthreads();

    float s = 0.f;
#pragma unroll
    for (int i = 0; i < 4; i++) {
        v4[i] = __expf(v4[i] - m);
        s += v4[i];
    }
    red[tid] = s;
    __syncthreads();
    for (int off = 128; off; off >>= 1) {
        if (tid < off) red[tid] += red[tid + off];
        __syncthreads();
    }
    float inv = 1.f / red[0];
#pragma unroll
    for (int i = 0; i < 4; i++) p[tid + i * 256] = v4[i] * inv;
}

// ---------------- host orchestration ----------------
static void launch_gemm(const float* A, const float* B, const float* bias, const float* mulb,
                        const float* resb, float* C, int M, int N, int K, int lda, int ldb,
                        int ldc, int act, int batch = 1, long sA = 0, long sB = 0, long sC = 0) {
    dim3 g((N + 63) / 64, (M + 63) / 64, batch);
    gemm_k<<<g, 128>>>(A, B, bias, mulb, resb, C, M, N, K, lda, ldb, ldc, sA, sB, sC, act);
}

extern "C" void kernel_launch(void* const* d_in, const int* in_sizes, int n_in,
                              void* d_out, int out_size) {
    const int* ids = (const int*)d_in[0];
    const float* emb = (const float*)d_in[1];
    const float* enc_Wq = (const float*)d_in[2];
    const float* enc_Wk = (const float*)d_in[3];
    const float* enc_Wv = (const float*)d_in[4];
    const float* enc_Wb = (const float*)d_in[5];
    const float* enc_nw = (const float*)d_in[6];
    const float* enc_Wo = (const float*)d_in[7];
    const float* ck_W = (const float*)d_in[8];
    const float* ck_b = (const float*)d_in[9];
    const float* cv_W = (const float*)d_in[10];
    const float* cv_b = (const float*)d_in[11];
    const float* dn_Wq = (const float*)d_in[12];
    const float* dn_Wk = (const float*)d_in[13];
    const float* dn_Wv = (const float*)d_in[14];
    const float* dn_Wb = (const float*)d_in[15];
    const float* dn_nw = (const float*)d_in[16];
    const float* dn_Wo = (const float*)d_in[17];
    const float* sw_in_w = (const float*)d_in[18];
    const float* sw_post_w = (const float*)d_in[19];
    const float* sw_Wq = (const float*)d_in[20];
    const float* sw_Wo = (const float*)d_in[21];
    const float* sw_up_W = (const float*)d_in[22];
    const float* sw_up_b = (const float*)d_in[23];
    const float* sw_gate_W = (const float*)d_in[24];
    const float* sw_gate_b = (const float*)d_in[25];
    const float* sw_down_W = (const float*)d_in[26];
    const float* sw_down_b = (const float*)d_in[27];
    const float* final_w = (const float*)d_in[28];

    float *hs, *hbuf, *q, *k, *v, *beta, *o, *kc, *vc, *kcr, *scores, *ff1, *ff2, *ct, *st;
    cudaGetSymbolAddress((void**)&hs, g_hs);
    cudaGetSymbolAddress((void**)&hbuf, g_hbuf);
    cudaGetSymbolAddress((void**)&q, g_q);
    cudaGetSymbolAddress((void**)&k, g_k);
    cudaGetSymbolAddress((void**)&v, g_v);
    cudaGetSymbolAddress((void**)&beta, g_beta);
    cudaGetSymbolAddress((void**)&o, g_o);
    cudaGetSymbolAddress((void**)&kc, g_kc);
    cudaGetSymbolAddress((void**)&vc, g_vc);
    cudaGetSymbolAddress((void**)&kcr, g_kcr);
    cudaGetSymbolAddress((void**)&scores, g_scores);
    cudaGetSymbolAddress((void**)&ff1, g_ff1);
    cudaGetSymbolAddress((void**)&ff2, g_ff2);
    cudaGetSymbolAddress((void**)&ct, g_cos);
    cudaGetSymbolAddress((void**)&st, g_sin);

    embed_k<<<T, 256>>>(ids, emb, hs);
    rope_tab_k<<<T, 32>>>(ct, st);

    auto deltanet = [&](const float* Wq, const float* Wk, const float* Wv, const float* Wb,
                        const float* nw, const float* Wo) {
        launch_gemm(hs, Wq, nullptr, nullptr, nullptr, q, T, D, D, D, D, D, 1);
        launch_gemm(hs, Wk, nullptr, nullptr, nullptr, k, T, D, D, D, D, D, 1);
        launch_gemm(hs, Wv, nullptr, nullptr, nullptr, v, T, D, D, D, D, D, 1);
        launch_gemm(hs, Wb, nullptr, nullptr, nullptr, beta, T, H, D, D, H, H, 2);
        groupnorm64_k<<<T * H / 8, 256>>>(q, nullptr, 0);
        groupnorm64_k<<<T * H / 8, 256>>>(k, nullptr, 0);
        deltanet_scan_k<<<H, 256>>>(q, k, v, beta, o);
        groupnorm64_k<<<T * H / 8, 256>>>(o, nw, 1);
        launch_gemm(o, Wo, nullptr, nullptr, nullptr, hs, T, D, D, D, D, D, 0);
    };

    for (int l = 0; l < 4; l++)
        deltanet(enc_Wq + (long)l * D * D, enc_Wk + (long)l * D * D, enc_Wv + (long)l * D * D,
                 enc_Wb + (long)l * D * H, enc_nw + (long)l * DHD, enc_Wo + (long)l * D * D);

    launch_gemm(hs, ck_W, ck_b, nullptr, nullptr, kc, T, D, D, D, D, D, 0);
    launch_gemm(hs, cv_W, cv_b, nullptr, nullptr, vc, T, D, D, D, D, D, 0);
    rope_apply_k<<<(T * H * 32 + 255) / 256, 256>>>(kc, kcr, ct, st);

    auto switcher = [&](int j) {
        rmsnorm_row_k<<<T, 256>>>(hs, sw_in_w + (long)j * D, hbuf);
        launch_gemm(hbuf, sw_Wq + (long)j * D * D, nullptr, nullptr, nullptr, q, T, D, D, D, D, D, 0);
        rope_apply_k<<<(T * H * 32 + 255) / 256, 256>>>(q, q, ct, st);
        attn_scores_k<<<dim3(T / 32, T / 32, H), 256>>>(q, kcr, scores);
        softmax_k<<<H * T, 256>>>(scores);
        launch_gemm(scores, vc, nullptr, nullptr, nullptr, o, T, DHD, T, T, D, D, 0,
                    H, (long)T * T, 64, 64);
        launch_gemm(o, sw_Wo + (long)j * D * D, nullptr, nullptr, hs, hs, T, D, D, D, D, D, 0);
        rmsnorm_row_k<<<T, 256>>>(hs, sw_post_w + (long)j * D, hbuf);
        launch_gemm(hbuf, sw_up_W + (long)j * D * DFF, sw_up_b + (long)j * DFF, nullptr, nullptr,
                    ff1, T, DFF, D, D, DFF, DFF, 0);
        launch_gemm(hbuf, sw_gate_W + (long)j * D * DFF, sw_gate_b + (long)j * DFF, ff1, nullptr,
                    ff2, T, DFF, D, D, DFF, DFF, 2);
        launch_gemm(ff2, sw_down_W + (long)j * DFF * D, sw_down_b + (long)j * D, nullptr, hs, hs,
                    T, D, DFF, DFF, D, D, 0);
    };

    switcher(0);
    deltanet(dn_Wq, dn_Wk, dn_Wv, dn_Wb, dn_nw, dn_Wo);
    switcher(1);
    deltanet(dn_Wq + (long)D * D, dn_Wk + (long)D * D, dn_Wv + (long)D * D,
             dn_Wb + (long)D * H, dn_nw + DHD, dn_Wo + (long)D * D);

    rmsnorm_row_k<<<T, 256>>>(hs, final_w, (float*)d_out);
}

// round 3
// speedup vs baseline: 2.3878x; 2.3878x over previous
#include <cuda_runtime.h>
#include <cuda_bf16.h>

#define T 1024
#define D 1024
#define H 16
#define DHD 64
#define DFF 4096

// ---------------- static scratch (device globals; no allocation) ----------------
__device__ float g_hs[T * D];
__device__ float g_hbuf[T * D];
__device__ float g_q[T * D];
__device__ float g_k[T * D];
__device__ float g_v[T * D];
__device__ float g_beta[T * H];
__device__ float g_o[T * D];
__device__ float g_kc[T * D];
__device__ float g_vc[T * D];
__device__ float g_kcr[T * D];
__device__ float g_scores[(size_t)H * T * T];
__device__ float g_ff1[T * DFF];
__device__ float g_ff2[T * DFF];
__device__ float g_cos[T * 32];
__device__ float g_sin[T * 32];

// ---------------- embedding gather ----------------
__global__ void embed_k(const int* __restrict__ ids, const float* __restrict__ emb,
                        float* __restrict__ out) {
    int t = blockIdx.x;
    int id = ids[t];
    for (int i = threadIdx.x; i < D; i += 256)
        out[(size_t)t * D + i] = emb[(size_t)id * D + i];
}

// ---------------- rope tables ----------------
__global__ void rope_tab_k(float* __restrict__ ct, float* __restrict__ st) {
    int t = blockIdx.x, i = threadIdx.x;  // i in [0,32)
    float inv = __powf(10000.0f, -(float)i / 32.0f);
    float f = (float)t * inv;
    ct[t * 32 + i] = cosf(f);
    st[t * 32 + i] = sinf(f);
}

// rope apply on [T, H, 64]; in may equal out
__global__ void rope_apply_k(const float* __restrict__ in, float* __restrict__ out,
                             const float* __restrict__ ct, const float* __restrict__ st) {
    int idx = blockIdx.x * 256 + threadIdx.x;  // T*H*32 total
    if (idx >= T * H * 32) return;
    int d = idx & 31;
    int th = idx >> 5;
    int h = th & (H - 1);
    int t = th >> 4;
    float c = ct[t * 32 + d], s = st[t * 32 + d];
    const float* pi = in + (size_t)t * D + h * DHD;
    float* po = out + (size_t)t * D + h * DHD;
    float x0 = pi[d], x1 = pi[d + 32];
    po[d] = x0 * c - x1 * s;
    po[d + 32] = x1 * c + x0 * s;
}

// ---------------- tf32 helpers ----------------
__device__ __forceinline__ unsigned f2tf(float x) {
    unsigned r;
    asm("cvt.rna.tf32.f32 %0, %1;" : "=r"(r) : "f"(x));
    return r;
}
__device__ __forceinline__ void tf_split(float x, unsigned& hi, unsigned& lo) {
    hi = f2tf(x);
    lo = f2tf(x - __uint_as_float(hi));
}
__device__ __forceinline__ void mma_tf32(float* d, unsigned a0, unsigned a1, unsigned a2,
                                         unsigned a3, unsigned b0, unsigned b1) {
    asm volatile(
        "mma.sync.aligned.m16n8k8.row.col.f32.tf32.tf32.f32 "
        "{%0,%1,%2,%3}, {%4,%5,%6,%7}, {%8,%9}, {%0,%1,%2,%3};"
        : "+f"(d[0]), "+f"(d[1]), "+f"(d[2]), "+f"(d[3])
        : "r"(a0), "r"(a1), "r"(a2), "r"(a3), "r"(b0), "r"(b1));
}

// ---------------- tensor-core GEMM (3xTF32, fp32-accurate) ----------------
// C = act(A@B + bias) [*mul] [+res].  Requires M%64==0, N%64==0, K%16==0.
// 64x64x16 tile, 256 threads = 8 warps in 2x4 grid, warp tile 32x16.
__global__ __launch_bounds__(256) void tcgemm_k(
        const float* __restrict__ A, const float* __restrict__ Bm,
        const float* __restrict__ bias, const float* __restrict__ mulb,
        const float* __restrict__ resb, float* __restrict__ C,
        int M, int N, int K, int lda, int ldb, int ldc,
        long sA, long sB, long sC, int act) {
    int bz = blockIdx.z;
    A += (long)bz * sA;
    Bm += (long)bz * sB;
    C += (long)bz * sC;
    const float* mulp = mulb ? mulb + (long)bz * sC : nullptr;
    const float* resp = resb ? resb + (long)bz * sC : nullptr;

    int bm = blockIdx.y * 64, bn = blockIdx.x * 64;

    __shared__ float As[64][17];  // [m][k], padded
    __shared__ float Bs[16][68];  // [k][n], padded

    int tid = threadIdx.x;
    int lane = tid & 31;
    int warp = tid >> 5;
    int wm = warp >> 2;   // 0..1 -> rows wm*32
    int wn = warp & 3;    // 0..3 -> cols wn*16
    int grp = lane >> 2;  // 0..7
    int tig = lane & 3;   // 0..3

    // global staging maps
    int arow = tid >> 2;            // 0..63
    int acol = (tid & 3) * 4;       // 0,4,8,12
    int brow = tid >> 4;            // 0..15
    int bcol = (tid & 15) * 4;      // 0..60

    float4 aR, bR;
    auto gload = [&](int k0) {
        aR = *(const float4*)(A + (long)(bm + arow) * lda + k0 + acol);
        bR = *(const float4*)(Bm + (long)(k0 + brow) * ldb + bn + bcol);
    };
    auto sstore = [&]() {
        As[arow][acol + 0] = aR.x;
        As[arow][acol + 1] = aR.y;
        As[arow][acol + 2] = aR.z;
        As[arow][acol + 3] = aR.w;
        Bs[brow][bcol + 0] = bR.x;
        Bs[brow][bcol + 1] = bR.y;
        Bs[brow][bcol + 2] = bR.z;
        Bs[brow][bcol + 3] = bR.w;
    };

    float acc[2][2][4];
#pragma unroll
    for (int i = 0; i < 2; i++)
#pragma unroll
        for (int j = 0; j < 2; j++)
#pragma unroll
            for (int r = 0; r < 4; r++) acc[i][j][r] = 0.f;

    gload(0);
    sstore();
    __syncthreads();

    for (int k0 = 0; k0 < K; k0 += 16) {
        bool more = (k0 + 16) < K;
        if (more) gload(k0 + 16);

#pragma unroll
        for (int ks = 0; ks < 2; ks++) {
            int kk = ks * 8 + tig;
            // A fragments (2 m-tiles), split hi/lo
            unsigned ah[2][4], al[2][4];
#pragma unroll
            for (int mt = 0; mt < 2; mt++) {
                int m = wm * 32 + mt * 16 + grp;
                float a0 = As[m][kk];
                float a1 = As[m + 8][kk];
                float a2 = As[m][kk + 4];
                float a3 = As[m + 8][kk + 4];
                tf_split(a0, ah[mt][0], al[mt][0]);
                tf_split(a1, ah[mt][1], al[mt][1]);
                tf_split(a2, ah[mt][2], al[mt][2]);
                tf_split(a3, ah[mt][3], al[mt][3]);
            }
            // B fragments (2 n-tiles), split hi/lo
            unsigned bh[2][2], bl[2][2];
#pragma unroll
            for (int nt = 0; nt < 2; nt++) {
                int n = wn * 16 + nt * 8 + grp;
                float b0 = Bs[ks * 8 + tig][n];
                float b1 = Bs[ks * 8 + tig + 4][n];
                tf_split(b0, bh[nt][0], bl[nt][0]);
                tf_split(b1, bh[nt][1], bl[nt][1]);
            }
#pragma unroll
            for (int mt = 0; mt < 2; mt++)
#pragma unroll
                for (int nt = 0; nt < 2; nt++) {
                    float* d = acc[mt][nt];
                    mma_tf32(d, ah[mt][0], ah[mt][1], ah[mt][2], ah[mt][3],
                             bh[nt][0], bh[nt][1]);
                    mma_tf32(d, al[mt][0], al[mt][1], al[mt][2], al[mt][3],
                             bh[nt][0], bh[nt][1]);
                    mma_tf32(d, ah[mt][0], ah[mt][1], ah[mt][2], ah[mt][3],
                             bl[nt][0], bl[nt][1]);
                }
        }
        __syncthreads();
        if (more) {
            sstore();
            __syncthreads();
        }
    }

    // epilogue
#pragma unroll
    for (int mt = 0; mt < 2; mt++)
#pragma unroll
        for (int nt = 0; nt < 2; nt++)
#pragma unroll
            for (int r = 0; r < 4; r++) {
                int gm = bm + wm * 32 + mt * 16 + grp + (r >> 1) * 8;
                int gn = bn + wn * 16 + nt * 8 + tig * 2 + (r & 1);
                float v = acc[mt][nt][r];
                if (bias) v += bias[gn];
                if (act == 1) v = v / (1.f + __expf(-v));
                else if (act == 2) v = 1.f / (1.f + __expf(-v));
                if (mulp) v *= mulp[(long)gm * ldc + gn];
                if (resp) v += resp[(long)gm * ldc + gn];
                C[(long)gm * ldc + gn] = v;
            }
}

// ---------------- SIMT GEMM fallback (small N; R1 version) ----------------
__global__ void gemm_k(const float* __restrict__ A, const float* __restrict__ Bm,
                       const float* __restrict__ bias, const float* __restrict__ mulb,
                       const float* __restrict__ resb, float* __restrict__ C,
                       int M, int N, int K, int lda, int ldb, int ldc,
                       long sA, long sB, long sC, int act) {
    int bz = blockIdx.z;
    A += (long)bz * sA;
    Bm += (long)bz * sB;
    C += (long)bz * sC;
    const float* mulp = mulb ? mulb + (long)bz * sC : nullptr;
    const float* resp = resb ? resb + (long)bz * sC : nullptr;

    int bm = blockIdx.y * 64, bn = blockIdx.x * 64;
    __shared__ float As[16][68];
    __shared__ float Bs[16][68];
    int tid = threadIdx.x;
    int ty = tid >> 4, tx = tid & 15;
    int aRow = tid >> 2;
    int aColBase = (tid & 3) * 4;
    int bRow = tid >> 4;
    int bColBase = (tid & 15) * 4;

    float acc[4][4];
#pragma unroll
    for (int i = 0; i < 4; i++)
#pragma unroll
        for (int j = 0; j < 4; j++) acc[i][j] = 0.f;

    for (int k0 = 0; k0 < K; k0 += 16) {
#pragma unroll
        for (int i = 0; i < 4; i++) {
            int kk = aColBase + i;
            int gm = bm + aRow, gk = k0 + kk;
            float val = (gm < M) ? A[(long)gm * lda + gk] : 0.f;
            As[kk][aRow] = val;
        }
#pragma unroll
        for (int i = 0; i < 4; i++) {
            int nn = bColBase + i;
            int gn = bn + nn, gk = k0 + bRow;
            float val = (gn < N) ? Bm[(long)gk * ldb + gn] : 0.f;
            Bs[bRow][nn] = val;
        }
        __syncthreads();
#pragma unroll
        for (int kk = 0; kk < 16; kk++) {
            float a[4], b[4];
#pragma unroll
            for (int i = 0; i < 4; i++) a[i] = As[kk][ty * 4 + i];
#pragma unroll
            for (int i = 0; i < 4; i++) b[i] = Bs[kk][tx * 4 + i];
#pragma unroll
            for (int i = 0; i < 4; i++)
#pragma unroll
                for (int j = 0; j < 4; j++) acc[i][j] += a[i] * b[j];
        }
        __syncthreads();
    }

#pragma unroll
    for (int i = 0; i < 4; i++) {
        int gm = bm + ty * 4 + i;
        if (gm >= M) continue;
#pragma unroll
        for (int j = 0; j < 4; j++) {
            int gn = bn + tx * 4 + j;
            if (gn >= N) continue;
            float v = acc[i][j];
            if (bias) v += bias[gn];
            if (act == 1) v = v / (1.f + __expf(-v));
            else if (act == 2) v = 1.f / (1.f + __expf(-v));
            if (mulp) v *= mulp[(long)gm * ldc + gn];
            if (resp) v += resp[(long)gm * ldc + gn];
            C[(long)gm * ldc + gn] = v;
        }
    }
}

// ---------------- group norm over 64 (l2norm or rmsnorm*w) ----------------
__global__ void groupnorm64_k(float* __restrict__ x, const float* __restrict__ w, int mode) {
    int g = blockIdx.x * 8 + (threadIdx.x >> 5);  // group over T*H
    int lane = threadIdx.x & 31;
    float* p = x + (size_t)g * 64;
    float a = p[lane], b = p[lane + 32];
    float s = a * a + b * b;
#pragma unroll
    for (int off = 16; off; off >>= 1) s += __shfl_xor_sync(0xffffffffu, s, off);
    float r = (mode == 0) ? rsqrtf(s + 1e-6f) : rsqrtf(s * (1.f / 64.f) + 1e-6f);
    float wa = mode ? w[lane] : 1.f;
    float wb = mode ? w[lane + 32] : 1.f;
    p[lane] = a * r * wa;
    p[lane + 32] = b * r * wb;
}

// ---------------- row rmsnorm over D ----------------
__global__ void rmsnorm_row_k(const float* __restrict__ x, const float* __restrict__ w,
                              float* __restrict__ out) {
    int t = blockIdx.x;
    const float* p = x + (size_t)t * D;
    __shared__ float red[256];
    float s = 0.f;
    for (int i = threadIdx.x; i < D; i += 256) {
        float v = p[i];
        s += v * v;
    }
    red[threadIdx.x] = s;
    __syncthreads();
    for (int off = 128; off; off >>= 1) {
        if (threadIdx.x < off) red[threadIdx.x] += red[threadIdx.x + off];
        __syncthreads();
    }
    float r = rsqrtf(red[0] * (1.f / D) + 1e-6f);
    for (int i = threadIdx.x; i < D; i += 256)
        out[(size_t)t * D + i] = p[i] * r * w[i];
}

// ---------------- DeltaNet sequential scan ----------------
__global__ void deltanet_scan_k(const float* __restrict__ q, const float* __restrict__ k,
                                const float* __restrict__ v, const float* __restrict__ beta,
                                float* __restrict__ o) {
    int h = blockIdx.x;
    int tid = threadIdx.x;
    int j = tid >> 2;
    int r = tid & 3;
    __shared__ float sk[2][64], sq[2][64], sv[2][64], sb[2];

    float s[16];
#pragma unroll
    for (int i = 0; i < 16; i++) s[i] = 0.f;

    if (tid < 64) sk[0][tid] = k[(size_t)h * 64 + tid];
    else if (tid < 128) sq[0][tid - 64] = q[(size_t)h * 64 + (tid - 64)];
    else if (tid < 192) sv[0][tid - 128] = v[(size_t)h * 64 + (tid - 128)];
    else if (tid == 192) sb[0] = beta[h];
    __syncthreads();

    for (int t = 0; t < T; t++) {
        int cur = t & 1, nxt = cur ^ 1;
        float pre = 0.f;
        bool havePre = (t + 1 < T) && (tid <= 192);
        if (havePre) {
            int tt = t + 1;
            if (tid < 64) pre = k[(size_t)tt * D + h * 64 + tid];
            else if (tid < 128) pre = q[(size_t)tt * D + h * 64 + (tid - 64)];
            else if (tid < 192) pre = v[(size_t)tt * D + h * 64 + (tid - 128)];
            else pre = beta[tt * H + h];
        }

        float p0 = 0.f, p1 = 0.f;
#pragma unroll
        for (int i = 0; i < 16; i += 2) {
            p0 += sk[cur][r * 16 + i] * s[i];
            p1 += sk[cur][r * 16 + i + 1] * s[i + 1];
        }
        float p = p0 + p1;
        p += __shfl_xor_sync(0xffffffffu, p, 1);
        p += __shfl_xor_sync(0xffffffffu, p, 2);

        float delta = sb[cur] * (sv[cur][j] - p);

        float o0 = 0.f, o1 = 0.f;
#pragma unroll
        for (int i = 0; i < 16; i += 2) {
            s[i] += sk[cur][r * 16 + i] * delta;
            o0 += sq[cur][r * 16 + i] * s[i];
            s[i + 1] += sk[cur][r * 16 + i + 1] * delta;
            o1 += sq[cur][r * 16 + i + 1] * s[i + 1];
        }
        float oo = o0 + o1;
        oo += __shfl_xor_sync(0xffffffffu, oo, 1);
        oo += __shfl_xor_sync(0xffffffffu, oo, 2);
        if (r == 0) o[(size_t)t * D + h * 64 + j] = oo;

        if (havePre) {
            if (tid < 64) sk[nxt][tid] = pre;
            else if (tid < 128) sq[nxt][tid - 64] = pre;
            else if (tid < 192) sv[nxt][tid - 128] = pre;
            else sb[nxt] = pre;
        }
        __syncthreads();
    }
}

// ---------------- attention scores: per-head tril(QK^T)/8 ----------------
__global__ void attn_scores_k(const float* __restrict__ q, const float* __restrict__ kk,
                              float* __restrict__ scores) {
    int h = blockIdx.z;
    int t0 = blockIdx.y * 32, s0 = blockIdx.x * 32;
    size_t base = (size_t)h * T * T;
    int tid = threadIdx.x;

    if (s0 > t0 + 31) {  // fully masked tile
        for (int idx = tid; idx < 1024; idx += 256) {
            int tt = idx >> 5, ss = idx & 31;
            scores[base + (size_t)(t0 + tt) * T + s0 + ss] = -1e30f;
        }
        return;
    }

    __shared__ float sQ[32][65], sK[32][65];
    for (int idx = tid; idx < 2048; idx += 256) {
        int rr = idx >> 6, cc = idx & 63;
        sQ[rr][cc] = q[(size_t)(t0 + rr) * D + h * 64 + cc];
        sK[rr][cc] = kk[(size_t)(s0 + rr) * D + h * 64 + cc];
    }
    __syncthreads();

    int sl = tid & 31, tg = tid >> 5;
#pragma unroll
    for (int i = 0; i < 4; i++) {
        int tt = tg + i * 8;
        float acc = 0.f;
#pragma unroll
        for (int d = 0; d < 64; d++) acc += sQ[tt][d] * sK[sl][d];
        int gt = t0 + tt, gs = s0 + sl;
        scores[base + (size_t)gt * T + gs] = (gs <= gt) ? acc * 0.125f : -1e30f;
    }
}

// ---------------- row softmax over 1024 ----------------
__global__ void softmax_k(float* __restrict__ scores) {
    size_t row = blockIdx.x;  // h*T + t
    float* p = scores + row * T;
    __shared__ float red[256];
    int tid = threadIdx.x;

    float v4[4];
    float m = -1e30f;
#pragma unroll
    for (int i = 0; i < 4; i++) {
        v4[i] = p[tid + i * 256];
        m = fmaxf(m, v4[i]);
    }
    red[tid] = m;
    __syncthreads();
    for (int off = 128; off; off >>= 1) {
        if (tid < off) red[tid] = fmaxf(red[tid], red[tid + off]);
        __syncthreads();
    }
    m = red[0];
    __syncthreads();

    float s = 0.f;
#pragma unroll
    for (int i = 0; i < 4; i++) {
        v4[i] = __expf(v4[i] - m);
        s += v4[i];
    }
    red[tid] = s;
    __syncthreads();
    for (int off = 128; off; off >>= 1) {
        if (tid < off) red[tid] += red[tid + off];
        __syncthreads();
    }
    float inv = 1.f / red[0];
#pragma unroll
    for (int i = 0; i < 4; i++) p[tid + i * 256] = v4[i] * inv;
}

// ---------------- host orchestration ----------------
static void launch_gemm(const float* A, const float* B, const float* bias, const float* mulb,
                        const float* resb, float* C, int M, int N, int K, int lda, int ldb,
                        int ldc, int act, int batch = 1, long sA = 0, long sB = 0, long sC = 0) {
    if ((M % 64 == 0) && (N % 64 == 0) && (K % 16 == 0)) {
        dim3 g(N / 64, M / 64, batch);
        tcgemm_k<<<g, 256>>>(A, B, bias, mulb, resb, C, M, N, K, lda, ldb, ldc, sA, sB, sC, act);
    } else {
        dim3 g((N + 63) / 64, (M + 63) / 64, batch);
        gemm_k<<<g, 256>>>(A, B, bias, mulb, resb, C, M, N, K, lda, ldb, ldc, sA, sB, sC, act);
    }
}

extern "C" void kernel_launch(void* const* d_in, const int* in_sizes, int n_in,
                              void* d_out, int out_size) {
    const int* ids = (const int*)d_in[0];
    const float* emb = (const float*)d_in[1];
    const float* enc_Wq = (const float*)d_in[2];
    const float* enc_Wk = (const float*)d_in[3];
    const float* enc_Wv = (const float*)d_in[4];
    const float* enc_Wb = (const float*)d_in[5];
    const float* enc_nw = (const float*)d_in[6];
    const float* enc_Wo = (const float*)d_in[7];
    const float* ck_W = (const float*)d_in[8];
    const float* ck_b = (const float*)d_in[9];
    const float* cv_W = (const float*)d_in[10];
    const float* cv_b = (const float*)d_in[11];
    const float* dn_Wq = (const float*)d_in[12];
    const float* dn_Wk = (const float*)d_in[13];
    const float* dn_Wv = (const float*)d_in[14];
    const float* dn_Wb = (const float*)d_in[15];
    const float* dn_nw = (const float*)d_in[16];
    const float* dn_Wo = (const float*)d_in[17];
    const float* sw_in_w = (const float*)d_in[18];
    const float* sw_post_w = (const float*)d_in[19];
    const float* sw_Wq = (const float*)d_in[20];
    const float* sw_Wo = (const float*)d_in[21];
    const float* sw_up_W = (const float*)d_in[22];
    const float* sw_up_b = (const float*)d_in[23];
    const float* sw_gate_W = (const float*)d_in[24];
    const float* sw_gate_b = (const float*)d_in[25];
    const float* sw_down_W = (const float*)d_in[26];
    const float* sw_down_b = (const float*)d_in[27];
    const float* final_w = (const float*)d_in[28];

    float *hs, *hbuf, *q, *k, *v, *beta, *o, *kc, *vc, *kcr, *scores, *ff1, *ff2, *ct, *st;
    cudaGetSymbolAddress((void**)&hs, g_hs);
    cudaGetSymbolAddress((void**)&hbuf, g_hbuf);
    cudaGetSymbolAddress((void**)&q, g_q);
    cudaGetSymbolAddress((void**)&k, g_k);
    cudaGetSymbolAddress((void**)&v, g_v);
    cudaGetSymbolAddress((void**)&beta, g_beta);
    cudaGetSymbolAddress((void**)&o, g_o);
    cudaGetSymbolAddress((void**)&kc, g_kc);
    cudaGetSymbolAddress((void**)&vc, g_vc);
    cudaGetSymbolAddress((void**)&kcr, g_kcr);
    cudaGetSymbolAddress((void**)&scores, g_scores);
    cudaGetSymbolAddress((void**)&ff1, g_ff1);
    cudaGetSymbolAddress((void**)&ff2, g_ff2);
    cudaGetSymbolAddress((void**)&ct, g_cos);
    cudaGetSymbolAddress((void**)&st, g_sin);

    embed_k<<<T, 256>>>(ids, emb, hs);
    rope_tab_k<<<T, 32>>>(ct, st);

    auto deltanet = [&](const float* Wq, const float* Wk, const float* Wv, const float* Wb,
                        const float* nw, const float* Wo) {
        launch_gemm(hs, Wq, nullptr, nullptr, nullptr, q, T, D, D, D, D, D, 1);
        launch_gemm(hs, Wk, nullptr, nullptr, nullptr, k, T, D, D, D, D, D, 1);
        launch_gemm(hs, Wv, nullptr, nullptr, nullptr, v, T, D, D, D, D, D, 1);
        launch_gemm(hs, Wb, nullptr, nullptr, nullptr, beta, T, H, D, D, H, H, 2);
        groupnorm64_k<<<T * H / 8, 256>>>(q, nullptr, 0);
        groupnorm64_k<<<T * H / 8, 256>>>(k, nullptr, 0);
        deltanet_scan_k<<<H, 256>>>(q, k, v, beta, o);
        groupnorm64_k<<<T * H / 8, 256>>>(o, nw, 1);
        launch_gemm(o, Wo, nullptr, nullptr, nullptr, hs, T, D, D, D, D, D, 0);
    };

    for (int l = 0; l < 4; l++)
        deltanet(enc_Wq + (long)l * D * D, enc_Wk + (long)l * D * D, enc_Wv + (long)l * D * D,
                 enc_Wb + (long)l * D * H, enc_nw + (long)l * DHD, enc_Wo + (long)l * D * D);

    launch_gemm(hs, ck_W, ck_b, nullptr, nullptr, kc, T, D, D, D, D, D, 0);
    launch_gemm(hs, cv_W, cv_b, nullptr, nullptr, vc, T, D, D, D, D, D, 0);
    rope_apply_k<<<(T * H * 32 + 255) / 256, 256>>>(kc, kcr, ct, st);

    auto switcher = [&](int j) {
        rmsnorm_row_k<<<T, 256>>>(hs, sw_in_w + (long)j * D, hbuf);
        launch_gemm(hbuf, sw_Wq + (long)j * D * D, nullptr, nullptr, nullptr, q, T, D, D, D, D, D, 0);
        rope_apply_k<<<(T * H * 32 + 255) / 256, 256>>>(q, q, ct, st);
        attn_scores_k<<<dim3(T / 32, T / 32, H), 256>>>(q, kcr, scores);
        softmax_k<<<H * T, 256>>>(scores);
        launch_gemm(scores, vc, nullptr, nullptr, nullptr, o, T, DHD, T, T, D, D, 0,
                    H, (long)T * T, 64, 64);
        launch_gemm(o, sw_Wo + (long)j * D * D, nullptr, nullptr, hs, hs, T, D, D, D, D, D, 0);
        rmsnorm_row_k<<<T, 256>>>(hs, sw_post_w + (long)j * D, hbuf);
        launch_gemm(hbuf, sw_up_W + (long)j * D * DFF, sw_up_b + (long)j * DFF, nullptr, nullptr,
                    ff1, T, DFF, D, D, DFF, DFF, 0);
        launch_gemm(hbuf, sw_gate_W + (long)j * D * DFF, sw_gate_b + (long)j * DFF, ff1, nullptr,
                    ff2, T, DFF, D, D, DFF, DFF, 2);
        launch_gemm(ff2, sw_down_W + (long)j * DFF * D, sw_down_b + (long)j * D, nullptr, hs, hs,
                    T, D, DFF, DFF, D, D, 0);
    };

    switcher(0);
    deltanet(dn_Wq, dn_Wk, dn_Wv, dn_Wb, dn_nw, dn_Wo);
    switcher(1);
    deltanet(dn_Wq + (long)D * D, dn_Wk + (long)D * D, dn_Wv + (long)D * D,
             dn_Wb + (long)D * H, dn_nw + DHD, dn_Wo + (long)D * D);

    rmsnorm_row_k<<<T, 256>>>(hs, final_w, (float*)d_out);
}